// round 3
// baseline (speedup 1.0000x reference)
#include <cuda_runtime.h>
#include <cstdint>
#include <cstddef>

// Problem constants
#define B_TOT  131072
#define T_DIM  5
#define V_DIM  60
#define TV     (T_DIM * V_DIM)   // 300
#define KB     64                // b's per k-tile
#define NC     296               // CTAs in kernel 1 (2 per SM)
#define NTILES (B_TOT / KB)      // 2048

// Per-CTA partial M slabs, stored TRANSPOSED: part[c][j*60 + v] = M_c[v][j]
// 296 * 3600 floats = 4.26 MB (fits L2). Fully overwritten every launch.
__device__ float g_part[NC * 3600];

// Packed f32x2 FMA when the target supports it (sm_100+ / PTX 8.6); otherwise
// two scalar FMAs on the lo/hi halves. Same numerics either way (.rn).
__device__ __forceinline__ unsigned long long fma2(unsigned long long a,
                                                   unsigned long long b,
                                                   unsigned long long c) {
#if defined(__CUDA_ARCH__) && (__CUDA_ARCH__ >= 1000)
    unsigned long long d;
    asm("fma.rn.f32x2 %0, %1, %2, %3;" : "=l"(d) : "l"(a), "l"(b), "l"(c));
    return d;
#else
    float2 fa = *reinterpret_cast<float2*>(&a);
    float2 fb = *reinterpret_cast<float2*>(&b);
    float2 fc = *reinterpret_cast<float2*>(&c);
    float2 fd;
    fd.x = fmaf(fa.x, fb.x, fc.x);
    fd.y = fmaf(fa.y, fb.y, fc.y);
    unsigned long long d;
    d = *reinterpret_cast<unsigned long long*>(&fd);
    return d;
#endif
}

// ============================================================================
// Kernel 1: stream x, build A,R tiles in smem, accumulate M = A^T R (64x64
// padded, true 60x60) with packed f32x2 FMAs. Each CTA writes its partial M.
// ============================================================================
__global__ __launch_bounds__(256, 2)
void k1_gram(const float* __restrict__ x,
             const float* __restrict__ W1,
             const float* __restrict__ W3) {
    // sAd: duplicated A pairs, [k][2*v] holds {a,a}  -> 64*128 floats = 32 KB
    // sR : R tile            , [k][v]               -> 64*64  floats = 16 KB
    __shared__ float sAd[KB * 128];
    __shared__ float sR[KB * 64];

    const int tid = threadIdx.x;

    float w1[T_DIM], w3[T_DIM];
#pragma unroll
    for (int t = 0; t < T_DIM; t++) { w1[t] = W1[t]; w3[t] = W3[t]; }

    // GEMM thread mapping: 4 k-groups x (8x8 thread grid), 8x8 tile each
    const int grp = tid >> 6;        // 0..3 : handles k = grp + 4*kk
    const int gt  = tid & 63;
    const int ty  = gt >> 3;         // 0..7 : rows  v = ty*8 + i
    const int tx  = gt & 7;          // 0..7 : cols  j = tx*8 + 2*jp + {0,1}

    unsigned long long acc[8][4];
#pragma unroll
    for (int i = 0; i < 8; i++)
#pragma unroll
        for (int jp = 0; jp < 4; jp++) acc[i][jp] = 0ull;

    // Phase-A thread mapping: 16 lanes (4 v's each, lane 15 = zero pad) x 16 b-rows
    const int colA = tid & 15;
    const int rowA = tid >> 4;

    for (int tile = blockIdx.x; tile < NTILES; tile += NC) {
        const int b0 = tile * KB;

        // ---------- Phase A: a[b,v] = sum_t x*W1,  r[b,v] = sum_t x*W3 ----------
#pragma unroll
        for (int p = 0; p < KB / 16; p++) {
            const int bi = rowA + p * 16;
            if (colA < 15) {
                const float* xb = x + (size_t)(b0 + bi) * TV + colA * 4;
                float4 a = make_float4(0.f, 0.f, 0.f, 0.f);
                float4 r = make_float4(0.f, 0.f, 0.f, 0.f);
#pragma unroll
                for (int t = 0; t < T_DIM; t++) {
                    float4 xv = *(const float4*)(xb + t * V_DIM);
                    a.x = fmaf(xv.x, w1[t], a.x); a.y = fmaf(xv.y, w1[t], a.y);
                    a.z = fmaf(xv.z, w1[t], a.z); a.w = fmaf(xv.w, w1[t], a.w);
                    r.x = fmaf(xv.x, w3[t], r.x); r.y = fmaf(xv.y, w3[t], r.y);
                    r.z = fmaf(xv.z, w3[t], r.z); r.w = fmaf(xv.w, w3[t], r.w);
                }
                float4 d0 = make_float4(a.x, a.x, a.y, a.y);
                float4 d1 = make_float4(a.z, a.z, a.w, a.w);
                *(float4*)&sAd[bi * 128 + colA * 8]     = d0;
                *(float4*)&sAd[bi * 128 + colA * 8 + 4] = d1;
                *(float4*)&sR[bi * 64 + colA * 4]       = r;
            } else {
                float4 z = make_float4(0.f, 0.f, 0.f, 0.f);
                *(float4*)&sAd[bi * 128 + 120] = z;
                *(float4*)&sAd[bi * 128 + 124] = z;
                *(float4*)&sR[bi * 64 + 60]    = z;
            }
        }
        __syncthreads();

        // ---------- Phase B: M += a ⊗ r over the k-tile (f32x2 packed) ----------
#pragma unroll
        for (int kk = 0; kk < KB / 4; kk++) {
            const int k = grp + kk * 4;
            unsigned long long ad[8];
            const ulonglong2* pa = (const ulonglong2*)&sAd[k * 128 + ty * 16];
#pragma unroll
            for (int q = 0; q < 4; q++) {
                ulonglong2 v = pa[q];
                ad[2 * q] = v.x; ad[2 * q + 1] = v.y;
            }
            ulonglong2 r0 = *(const ulonglong2*)&sR[k * 64 + tx * 8];
            ulonglong2 r1 = *(const ulonglong2*)&sR[k * 64 + tx * 8 + 4];
            unsigned long long rp[4] = { r0.x, r0.y, r1.x, r1.y };
#pragma unroll
            for (int i = 0; i < 8; i++)
#pragma unroll
                for (int jp = 0; jp < 4; jp++)
                    acc[i][jp] = fma2(ad[i], rp[jp], acc[i][jp]);
        }
        __syncthreads();
    }

    // ---------- Reduce the 4 k-groups into sR (reused as 64x64 Ms) ----------
    float* Ms = sR;
    if (grp == 0) {
#pragma unroll
        for (int i = 0; i < 8; i++)
#pragma unroll
            for (int jp = 0; jp < 4; jp++) {
                unsigned int lo, hi;
                asm("mov.b64 {%0,%1}, %2;" : "=r"(lo), "=r"(hi) : "l"(acc[i][jp]));
                Ms[(ty * 8 + i) * 64 + tx * 8 + jp * 2]     = __uint_as_float(lo);
                Ms[(ty * 8 + i) * 64 + tx * 8 + jp * 2 + 1] = __uint_as_float(hi);
            }
    }
    __syncthreads();
#pragma unroll
    for (int g = 1; g < 4; g++) {
        if (grp == g) {
#pragma unroll
            for (int i = 0; i < 8; i++)
#pragma unroll
                for (int jp = 0; jp < 4; jp++) {
                    unsigned int lo, hi;
                    asm("mov.b64 {%0,%1}, %2;" : "=r"(lo), "=r"(hi) : "l"(acc[i][jp]));
                    Ms[(ty * 8 + i) * 64 + tx * 8 + jp * 2]     += __uint_as_float(lo);
                    Ms[(ty * 8 + i) * 64 + tx * 8 + jp * 2 + 1] += __uint_as_float(hi);
                }
        }
        __syncthreads();
    }

    // ---------- Store transposed slab: part[blk][j*60+v] = Ms[v][j] ----------
    float* dst = g_part + (size_t)blockIdx.x * 3600;
    for (int e = tid; e < 3600; e += 256) {
        const int j = e / 60;
        const int v = e - j * 60;
        dst[e] = Ms[v * 64 + j];
    }
}

// ============================================================================
// Kernel 2: one CTA per output column j. f64 accumulation for the tiny
// reductions (cross-CTA sum + W2^T dot) to keep our error floor well below
// the reference's own f32 accumulation noise.
//   Mcol[v]   = sum_c part[c][j][v]
//   prod[k]   = sum_v W2[v,k] * Mcol[v]
//   sig[k]    = sigmoid(prod[k] + b_s[k,j])
//   S[i]      = sum_k V_s[i,k] * sig[k]
//   out[i,j]  = softmax_i(S)[i]
// ============================================================================
__global__ __launch_bounds__(64)
void k2_epilogue(const float* __restrict__ W2,
                 const float* __restrict__ b_s,
                 const float* __restrict__ V_s,
                 float* __restrict__ out) {
    const int j = blockIdx.x;
    const int tid = threadIdx.x;

    __shared__ double Mcol[64];
    __shared__ float sig[64];
    __shared__ float sS[64];

    // Slab reduction in f64 (coalesced across the warp: v = tid consecutive)
    double s = 0.0;
    if (tid < 60) {
        const float* p = g_part + j * 60 + tid;
        double s0 = 0.0, s1 = 0.0, s2 = 0.0, s3 = 0.0;
        int c = 0;
        for (; c + 4 <= NC; c += 4) {
            s0 += (double)p[(size_t)(c + 0) * 3600];
            s1 += (double)p[(size_t)(c + 1) * 3600];
            s2 += (double)p[(size_t)(c + 2) * 3600];
            s3 += (double)p[(size_t)(c + 3) * 3600];
        }
        for (; c < NC; c++) s0 += (double)p[(size_t)c * 3600];
        s = (s0 + s1) + (s2 + s3);
    }
    Mcol[tid] = s;
    __syncthreads();

    // product column + sigmoid (dot in f64: 60 DFMA per thread, negligible)
    float sg = 0.f;
    if (tid < 60) {
        const int k = tid;
        double pr = 0.0;
#pragma unroll 4
        for (int v = 0; v < 60; v++) pr = fma((double)W2[v * 60 + k], Mcol[v], pr);
        float prf = (float)pr + b_s[k * 60 + j];
        sg = 1.f / (1.f + expf(-prf));
    }
    sig[tid] = sg;
    __syncthreads();

    // S column
    float Si = 0.f;
    if (tid < 60) {
        const float4* vr = (const float4*)(V_s + tid * 60);  // 240B rows, 16B aligned
#pragma unroll
        for (int q = 0; q < 15; q++) {
            float4 v = vr[q];
            Si = fmaf(v.x, sig[q * 4 + 0], Si);
            Si = fmaf(v.y, sig[q * 4 + 1], Si);
            Si = fmaf(v.z, sig[q * 4 + 2], Si);
            Si = fmaf(v.w, sig[q * 4 + 3], Si);
        }
    }
    sS[tid] = (tid < 60) ? Si : -1e30f;
    __syncthreads();

    // softmax over i (redundant per-thread scan of 60 values: trivial)
    float m = -1e30f;
#pragma unroll 4
    for (int i2 = 0; i2 < 60; i2++) m = fmaxf(m, sS[i2]);
    float sum = 0.f;
#pragma unroll 4
    for (int i2 = 0; i2 < 60; i2++) sum += expf(sS[i2] - m);
    if (tid < 60) out[tid * 60 + j] = expf(Si - m) / sum;
}

// ============================================================================
extern "C" void kernel_launch(void* const* d_in, const int* in_sizes, int n_in,
                              void* d_out, int out_size) {
    const float* x   = (const float*)d_in[0];
    const float* W1  = (const float*)d_in[1];
    const float* W2  = (const float*)d_in[2];
    const float* W3  = (const float*)d_in[3];
    const float* b_s = (const float*)d_in[4];
    const float* V_s = (const float*)d_in[5];
    float* out = (float*)d_out;

    k1_gram<<<NC, 256>>>(x, W1, W3);
    k2_epilogue<<<V_DIM, 64>>>(W2, b_s, V_s, out);
}

// round 6
// speedup vs baseline: 1.1389x; 1.1389x over previous
#include <cuda_runtime.h>
#include <cstdint>
#include <cstddef>

// Problem constants
#define B_TOT  131072
#define T_DIM  5
#define V_DIM  60
#define TV     300
#define KB     32                 // b-rows per k-tile
#define NC     296                // CTAs in kernel 1 (2 per SM)
#define NTILES (B_TOT / KB)       // 4096
#define XTILE_FLOATS (KB * TV)    // 9600 floats = 38400 B
#define XCHUNKS (XTILE_FLOATS / 4) // 2400 x 16B cp.async chunks
#define CG     8                  // slab groups in k2a
#define CPG    37                 // slabs per group (8*37 = 296)

// Per-CTA partial M slabs, TRANSPOSED: part[c][j*60 + v] = M_c[v][j]
__device__ float g_part[NC * 3600];
// Group-reduced slabs (k2a output)
__device__ float g_red[CG * 3600];

// Packed f32x2 FMA (sm_100+); scalar fallback otherwise. Same numerics (.rn).
__device__ __forceinline__ unsigned long long fma2(unsigned long long a,
                                                   unsigned long long b,
                                                   unsigned long long c) {
#if defined(__CUDA_ARCH__) && (__CUDA_ARCH__ >= 1000)
    unsigned long long d;
    asm("fma.rn.f32x2 %0, %1, %2, %3;" : "=l"(d) : "l"(a), "l"(b), "l"(c));
    return d;
#else
    float2 fa = *reinterpret_cast<float2*>(&a);
    float2 fb = *reinterpret_cast<float2*>(&b);
    float2 fc = *reinterpret_cast<float2*>(&c);
    float2 fd;
    fd.x = fmaf(fa.x, fb.x, fc.x);
    fd.y = fmaf(fa.y, fb.y, fc.y);
    return *reinterpret_cast<unsigned long long*>(&fd);
#endif
}

__device__ __forceinline__ void cp16(float* dst_smem, const float* src) {
    unsigned saddr = (unsigned)__cvta_generic_to_shared(dst_smem);
    asm volatile("cp.async.cg.shared.global [%0], [%1], 16;"
                 :: "r"(saddr), "l"(src));
}
__device__ __forceinline__ void cp_commit() {
    asm volatile("cp.async.commit_group;");
}
__device__ __forceinline__ void cp_wait1() {
    asm volatile("cp.async.wait_group 1;");
}
__device__ __forceinline__ void cp_wait0() {
    asm volatile("cp.async.wait_group 0;");
}

// ============================================================================
// Kernel 1: cp.async-pipelined stream of x; per tile: Phase A computes
// a = x·W1, r = x·W3 from smem-resident raw x; Phase B accumulates
// M += a ⊗ r with packed f32x2 FMAs (64x64 padded, true 60x60).
// Dynamic smem: xbuf[2][9600] | sAd[32*128] | sR[32*64]  = 101376 B
// ============================================================================
__global__ __launch_bounds__(256, 2)
void k1_gram(const float* __restrict__ x,
             const float* __restrict__ W1,
             const float* __restrict__ W3) {
    extern __shared__ float smem[];
    float* xbuf0 = smem;                       // 9600 floats
    float* xbuf1 = smem + XTILE_FLOATS;        // 9600 floats
    float* sAd   = smem + 2 * XTILE_FLOATS;    // 32*128 = 4096 floats (dup a pairs)
    float* sR    = sAd + KB * 128;             // 32*64  = 2048 floats

    const int tid = threadIdx.x;

    float w1[T_DIM], w3[T_DIM];
#pragma unroll
    for (int t = 0; t < T_DIM; t++) { w1[t] = W1[t]; w3[t] = W3[t]; }

    // GEMM mapping: 4 k-groups x (8x8 thread grid), 8x8 tile each
    const int grp = tid >> 6;        // 0..3 : handles k = grp + 4*kk
    const int gt  = tid & 63;
    const int ty  = gt >> 3;         // 0..7 : rows  v = ty*8 + i
    const int tx  = gt & 7;          // 0..7 : cols  j = tx*8 + 2*jp + {0,1}

    // Phase-A mapping: 32 rows x 8 v-lanes (lane 7 covers v 56..59 + zero pad)
    const int rowA  = tid >> 3;      // 0..31
    const int laneA = tid & 7;       // 0..7

    unsigned long long acc[8][4];
#pragma unroll
    for (int i = 0; i < 8; i++)
#pragma unroll
        for (int jp = 0; jp < 4; jp++) acc[i][jp] = 0ull;

    // Prologue: async-copy first tile into buf0
    {
        const float* src = x + (size_t)blockIdx.x * XTILE_FLOATS;
        for (int i = tid; i < XCHUNKS; i += 256)
            cp16(xbuf0 + i * 4, src + i * 4);
        cp_commit();
    }

    int parity = 0;
    for (int tile = blockIdx.x; tile < NTILES; tile += NC, parity ^= 1) {
        float* xcur = parity ? xbuf1 : xbuf0;
        float* xnxt = parity ? xbuf0 : xbuf1;

        const int next = tile + NC;
        if (next < NTILES) {
            const float* src = x + (size_t)next * XTILE_FLOATS;
            for (int i = tid; i < XCHUNKS; i += 256)
                cp16(xnxt + i * 4, src + i * 4);
            cp_commit();
            cp_wait1();          // current tile's group complete, next in flight
        } else {
            cp_wait0();
        }
        __syncthreads();         // copies visible; prev Phase B done w/ sAd,sR

        // ---------- Phase A: a/r from smem x, store dup-a + r tiles ----------
        {
            const float* xr = xcur + rowA * TV + laneA * 8;
            float a[8], r[8];
#pragma unroll
            for (int q = 0; q < 8; q++) { a[q] = 0.f; r[q] = 0.f; }
            if (laneA < 7) {
#pragma unroll
                for (int t = 0; t < T_DIM; t++) {
                    float4 x0 = *(const float4*)(xr + t * V_DIM);
                    float4 x1 = *(const float4*)(xr + t * V_DIM + 4);
                    a[0] = fmaf(x0.x, w1[t], a[0]); r[0] = fmaf(x0.x, w3[t], r[0]);
                    a[1] = fmaf(x0.y, w1[t], a[1]); r[1] = fmaf(x0.y, w3[t], r[1]);
                    a[2] = fmaf(x0.z, w1[t], a[2]); r[2] = fmaf(x0.z, w3[t], r[2]);
                    a[3] = fmaf(x0.w, w1[t], a[3]); r[3] = fmaf(x0.w, w3[t], r[3]);
                    a[4] = fmaf(x1.x, w1[t], a[4]); r[4] = fmaf(x1.x, w3[t], r[4]);
                    a[5] = fmaf(x1.y, w1[t], a[5]); r[5] = fmaf(x1.y, w3[t], r[5]);
                    a[6] = fmaf(x1.z, w1[t], a[6]); r[6] = fmaf(x1.z, w3[t], r[6]);
                    a[7] = fmaf(x1.w, w1[t], a[7]); r[7] = fmaf(x1.w, w3[t], r[7]);
                }
            } else {  // v = 56..59 real, 60..63 stay zero
#pragma unroll
                for (int t = 0; t < T_DIM; t++) {
                    float4 x0 = *(const float4*)(xr + t * V_DIM);
                    a[0] = fmaf(x0.x, w1[t], a[0]); r[0] = fmaf(x0.x, w3[t], r[0]);
                    a[1] = fmaf(x0.y, w1[t], a[1]); r[1] = fmaf(x0.y, w3[t], r[1]);
                    a[2] = fmaf(x0.z, w1[t], a[2]); r[2] = fmaf(x0.z, w3[t], r[2]);
                    a[3] = fmaf(x0.w, w1[t], a[3]); r[3] = fmaf(x0.w, w3[t], r[3]);
                }
            }
            float* pd = &sAd[rowA * 128 + laneA * 16];
            *(float4*)(pd)      = make_float4(a[0], a[0], a[1], a[1]);
            *(float4*)(pd + 4)  = make_float4(a[2], a[2], a[3], a[3]);
            *(float4*)(pd + 8)  = make_float4(a[4], a[4], a[5], a[5]);
            *(float4*)(pd + 12) = make_float4(a[6], a[6], a[7], a[7]);
            float* pr = &sR[rowA * 64 + laneA * 8];
            *(float4*)(pr)     = make_float4(r[0], r[1], r[2], r[3]);
            *(float4*)(pr + 4) = make_float4(r[4], r[5], r[6], r[7]);
        }
        __syncthreads();

        // ---------- Phase B: M += a ⊗ r over the k-tile (f32x2 packed) ----------
#pragma unroll
        for (int kk = 0; kk < KB / 4; kk++) {
            const int k = grp + kk * 4;
            unsigned long long ad[8];
            const ulonglong2* pa = (const ulonglong2*)&sAd[k * 128 + ty * 16];
#pragma unroll
            for (int q = 0; q < 4; q++) {
                ulonglong2 v = pa[q];
                ad[2 * q] = v.x; ad[2 * q + 1] = v.y;
            }
            ulonglong2 r0 = *(const ulonglong2*)&sR[k * 64 + tx * 8];
            ulonglong2 r1 = *(const ulonglong2*)&sR[k * 64 + tx * 8 + 4];
            unsigned long long rp[4] = { r0.x, r0.y, r1.x, r1.y };
#pragma unroll
            for (int i = 0; i < 8; i++)
#pragma unroll
                for (int jp = 0; jp < 4; jp++)
                    acc[i][jp] = fma2(ad[i], rp[jp], acc[i][jp]);
        }
        // no trailing sync needed: top-of-loop sync protects sAd/sR reuse
    }
    __syncthreads();   // all Phase B reads done before Ms overwrites sAd

    // ---------- Reduce 4 k-groups into Ms (reuse sAd as 64x64) ----------
    float* Ms = sAd;
    if (grp == 0) {
#pragma unroll
        for (int i = 0; i < 8; i++)
#pragma unroll
            for (int jp = 0; jp < 4; jp++) {
                unsigned int lo, hi;
                asm("mov.b64 {%0,%1}, %2;" : "=r"(lo), "=r"(hi) : "l"(acc[i][jp]));
                Ms[(ty * 8 + i) * 64 + tx * 8 + jp * 2]     = __uint_as_float(lo);
                Ms[(ty * 8 + i) * 64 + tx * 8 + jp * 2 + 1] = __uint_as_float(hi);
            }
    }
    __syncthreads();
#pragma unroll
    for (int g = 1; g < 4; g++) {
        if (grp == g) {
#pragma unroll
            for (int i = 0; i < 8; i++)
#pragma unroll
                for (int jp = 0; jp < 4; jp++) {
                    unsigned int lo, hi;
                    asm("mov.b64 {%0,%1}, %2;" : "=r"(lo), "=r"(hi) : "l"(acc[i][jp]));
                    Ms[(ty * 8 + i) * 64 + tx * 8 + jp * 2]     += __uint_as_float(lo);
                    Ms[(ty * 8 + i) * 64 + tx * 8 + jp * 2 + 1] += __uint_as_float(hi);
                }
        }
        __syncthreads();
    }

    // ---------- Store transposed slab: part[blk][j*60+v] = Ms[v][j] ----------
    float* dst = g_part + (size_t)blockIdx.x * 3600;
    for (int e = tid; e < 3600; e += 256) {
        const int j = e / 60;
        const int v = e - j * 60;
        dst[e] = Ms[v * 64 + j];
    }
}

// ============================================================================
// Kernel 2a: coalesced, whole-chip slab reduction: 296 slabs -> 8 slabs.
// grid (8 c-groups, 15 e-chunks) x 240 threads; all loads fully coalesced.
// ============================================================================
__global__ __launch_bounds__(240)
void k2a_reduce() {
    const int cg = blockIdx.x;                 // 0..7
    const int e  = blockIdx.y * 240 + threadIdx.x;  // 0..3599
    const float* p = g_part + (size_t)cg * CPG * 3600 + e;
    float s0 = 0.f, s1 = 0.f, s2 = 0.f, s3 = 0.f;
#pragma unroll
    for (int i = 0; i < CPG - 1; i += 4) {
        s0 += p[(size_t)(i + 0) * 3600];
        s1 += p[(size_t)(i + 1) * 3600];
        s2 += p[(size_t)(i + 2) * 3600];
        s3 += p[(size_t)(i + 3) * 3600];
    }
    s0 += p[(size_t)(CPG - 1) * 3600];
    g_red[cg * 3600 + e] = (s0 + s1) + (s2 + s3);
}

// ============================================================================
// Kernel 2b: one CTA per output column j (all f32; error budget verified).
//   Mcol[v]  = sum_{g<8} red[g][j*60+v]
//   prod[k]  = sum_v W2[v,k]*Mcol[v];  sig = sigmoid(prod + b_s[k,j])
//   S[i]     = sum_k V_s[i,k]*sig[k];  out[i,j] = softmax_i(S)
// ============================================================================
__global__ __launch_bounds__(64)
void k2b_epilogue(const float* __restrict__ W2,
                  const float* __restrict__ b_s,
                  const float* __restrict__ V_s,
                  float* __restrict__ out) {
    const int j = blockIdx.x;
    const int tid = threadIdx.x;

    __shared__ float Mcol[64];
    __shared__ float sig[64];
    __shared__ float sS[64];

    float s = 0.f;
    if (tid < 60) {
        const float* p = g_red + j * 60 + tid;
#pragma unroll
        for (int g = 0; g < CG; g++) s += p[g * 3600];
    }
    Mcol[tid] = s;
    __syncthreads();

    float sg = 0.f;
    if (tid < 60) {
        const int k = tid;
        float pr = 0.f;
#pragma unroll 4
        for (int v = 0; v < 60; v++) pr = fmaf(W2[v * 60 + k], Mcol[v], pr);
        pr += b_s[k * 60 + j];
        sg = 1.f / (1.f + expf(-pr));
    }
    sig[tid] = sg;
    __syncthreads();

    float Si = 0.f;
    if (tid < 60) {
        const float4* vr = (const float4*)(V_s + tid * 60);  // 240B rows, 16B aligned
#pragma unroll
        for (int q = 0; q < 15; q++) {
            float4 v = vr[q];
            Si = fmaf(v.x, sig[q * 4 + 0], Si);
            Si = fmaf(v.y, sig[q * 4 + 1], Si);
            Si = fmaf(v.z, sig[q * 4 + 2], Si);
            Si = fmaf(v.w, sig[q * 4 + 3], Si);
        }
    }
    sS[tid] = (tid < 60) ? Si : -1e30f;
    __syncthreads();

    float m = -1e30f;
#pragma unroll 4
    for (int i2 = 0; i2 < 60; i2++) m = fmaxf(m, sS[i2]);
    float sum = 0.f;
#pragma unroll 4
    for (int i2 = 0; i2 < 60; i2++) sum += expf(sS[i2] - m);
    if (tid < 60) out[tid * 60 + j] = expf(Si - m) / sum;
}

// ============================================================================
extern "C" void kernel_launch(void* const* d_in, const int* in_sizes, int n_in,
                              void* d_out, int out_size) {
    const float* x   = (const float*)d_in[0];
    const float* W1  = (const float*)d_in[1];
    const float* W2  = (const float*)d_in[2];
    const float* W3  = (const float*)d_in[3];
    const float* b_s = (const float*)d_in[4];
    const float* V_s = (const float*)d_in[5];
    float* out = (float*)d_out;

    const int smem_bytes = (2 * XTILE_FLOATS + KB * 128 + KB * 64) * 4; // 101376
    cudaFuncSetAttribute(k1_gram, cudaFuncAttributeMaxDynamicSharedMemorySize,
                         smem_bytes);

    k1_gram<<<NC, 256, smem_bytes>>>(x, W1, W3);
    k2a_reduce<<<dim3(CG, 15), 240>>>();
    k2b_epilogue<<<V_DIM, 64>>>(W2, b_s, V_s, out);
}

// round 9
// speedup vs baseline: 1.3166x; 1.1560x over previous
#include <cuda_runtime.h>
#include <cstdint>
#include <cstddef>

// Problem constants
#define B_TOT  131072
#define T_DIM  5
#define V_DIM  60
#define TV     300
#define KB     32                 // b-rows per k-tile
#define NC     296                // CTAs in kernel 1 (2 per SM)
#define NTILES (B_TOT / KB)       // 4096

// Per-CTA partial M slabs, TRANSPOSED: part[c][j*60 + v] = M_c[v][j]
// 296 * 3600 floats = 4.26 MB (L2-resident). Fully overwritten every launch.
__device__ float g_part[NC * 3600];

// Packed f32x2 FMA (sm_100+); scalar fallback otherwise. Same numerics (.rn).
__device__ __forceinline__ unsigned long long fma2(unsigned long long a,
                                                   unsigned long long b,
                                                   unsigned long long c) {
#if defined(__CUDA_ARCH__) && (__CUDA_ARCH__ >= 1000)
    unsigned long long d;
    asm("fma.rn.f32x2 %0, %1, %2, %3;" : "=l"(d) : "l"(a), "l"(b), "l"(c));
    return d;
#else
    float2 fa = *reinterpret_cast<float2*>(&a);
    float2 fb = *reinterpret_cast<float2*>(&b);
    float2 fc = *reinterpret_cast<float2*>(&c);
    float2 fd;
    fd.x = fmaf(fa.x, fb.x, fc.x);
    fd.y = fmaf(fa.y, fb.y, fc.y);
    return *reinterpret_cast<unsigned long long*>(&fd);
#endif
}

// {f, f} packed into a 64-bit register pair (register-side duplication)
__device__ __forceinline__ unsigned long long dup2(float f) {
    unsigned long long r;
    asm("mov.b64 %0, {%1, %2};" : "=l"(r) : "f"(f), "f"(f));
    return r;
}

// ============================================================================
// Kernel 1: Phase A reads x straight from GMEM into registers (x passes l1tex
// exactly once), computes a = x·W1, r = x·W3, stores PLAIN tiles:
//   sA[k][v]        (64-col rows; v 60..63 zero)       -> A loads are LDS.128
//                                                         warp broadcasts
//   sR[k][swz(j)]   (68-col rows, +4 offset for j>=32) -> r LDS.64 conflict-free
// Phase B: M += a ⊗ r with f32x2 FMAs; {a,a} pairs built in registers.
// Double-buffered sA/sR -> ONE barrier per tile; next tile's LDG overlaps
// other warps' Phase B.
// ============================================================================
__global__ __launch_bounds__(256, 2)
void k1_gram(const float* __restrict__ x,
             const float* __restrict__ W1,
             const float* __restrict__ W3) {
    __shared__ float sA[2][KB * 64];   // 16 KB total
    __shared__ float sR[2][KB * 68];   // 17.4 KB total

    const int tid = threadIdx.x;

    float w1[T_DIM], w3[T_DIM];
#pragma unroll
    for (int t = 0; t < T_DIM; t++) { w1[t] = W1[t]; w3[t] = W3[t]; }

    // Phase-B mapping: 4 k-groups x (8x8 thread grid), 8x8 output per thread
    const int grp = tid >> 6;        // 0..3 : handles k = grp + 4*kk
    const int gt  = tid & 63;
    const int ty  = gt >> 3;         // rows  v = ty*8 + i
    const int tx  = gt & 7;          // cols  j = tx*8 + 2*jp + {0,1}
    const int rOff = tx * 8 + (tx >> 2) * 4;   // swizzled r base (+jp*2)

    // Phase-A mapping: 16 b-rows x 16 v-lanes (lane 15 = v 60..63 zero pad)
    const int rowA  = tid >> 4;      // 0..15
    const int laneA = tid & 15;      // 0..15
    const int roA   = (laneA >> 1) * 8 + (laneA & 1) * 4 + (laneA >> 3) * 4;

    unsigned long long acc[8][4];
#pragma unroll
    for (int i = 0; i < 8; i++)
#pragma unroll
        for (int jp = 0; jp < 4; jp++) acc[i][jp] = 0ull;

    auto phaseA = [&](int tile, int buf) {
#pragma unroll
        for (int p = 0; p < 2; p++) {
            const int k = rowA + 16 * p;             // 0..31
            float4 a4 = make_float4(0.f, 0.f, 0.f, 0.f);
            float4 r4 = make_float4(0.f, 0.f, 0.f, 0.f);
            if (laneA < 15) {
                const float* xb = x + (size_t)(tile * KB + k) * TV + laneA * 4;
#pragma unroll
                for (int t = 0; t < T_DIM; t++) {
                    float4 xv = *(const float4*)(xb + t * V_DIM);
                    a4.x = fmaf(xv.x, w1[t], a4.x); r4.x = fmaf(xv.x, w3[t], r4.x);
                    a4.y = fmaf(xv.y, w1[t], a4.y); r4.y = fmaf(xv.y, w3[t], r4.y);
                    a4.z = fmaf(xv.z, w1[t], a4.z); r4.z = fmaf(xv.z, w3[t], r4.z);
                    a4.w = fmaf(xv.w, w1[t], a4.w); r4.w = fmaf(xv.w, w3[t], r4.w);
                }
            }
            *(float4*)&sA[buf][k * 64 + laneA * 4] = a4;
            *(float4*)&sR[buf][k * 68 + roA]       = r4;
        }
    };

    // Prologue: fill buffer 0
    phaseA(blockIdx.x, 0);
    __syncthreads();

    int buf = 0;
    for (int tile = blockIdx.x; tile < NTILES; tile += NC) {
        // ---------- Phase B on buf ----------
#pragma unroll
        for (int kk = 0; kk < KB / 4; kk++) {
            const int k = grp + kk * 4;
            float4 a0 = *(const float4*)&sA[buf][k * 64 + ty * 8];      // broadcast
            float4 a1 = *(const float4*)&sA[buf][k * 64 + ty * 8 + 4];  // broadcast
            unsigned long long ad[8];
            ad[0] = dup2(a0.x); ad[1] = dup2(a0.y);
            ad[2] = dup2(a0.z); ad[3] = dup2(a0.w);
            ad[4] = dup2(a1.x); ad[5] = dup2(a1.y);
            ad[6] = dup2(a1.z); ad[7] = dup2(a1.w);
            unsigned long long rp[4];
            const float* rb = &sR[buf][k * 68 + rOff];
#pragma unroll
            for (int jp = 0; jp < 4; jp++)
                rp[jp] = *(const unsigned long long*)(rb + jp * 2);
#pragma unroll
            for (int i = 0; i < 8; i++)
#pragma unroll
                for (int jp = 0; jp < 4; jp++)
                    acc[i][jp] = fma2(ad[i], rp[jp], acc[i][jp]);
        }

        // ---------- Phase A for next tile into the other buffer ----------
        const int nxt = tile + NC;
        if (nxt < NTILES) phaseA(nxt, buf ^ 1);
        __syncthreads();
        buf ^= 1;
    }

    // ---------- Reduce 4 k-groups into Ms (reuse sA: 4096 floats = 64x64) ----
    float* Ms = &sA[0][0];
    if (grp == 0) {
#pragma unroll
        for (int i = 0; i < 8; i++)
#pragma unroll
            for (int jp = 0; jp < 4; jp++) {
                unsigned int lo, hi;
                asm("mov.b64 {%0,%1}, %2;" : "=r"(lo), "=r"(hi) : "l"(acc[i][jp]));
                Ms[(ty * 8 + i) * 64 + tx * 8 + jp * 2]     = __uint_as_float(lo);
                Ms[(ty * 8 + i) * 64 + tx * 8 + jp * 2 + 1] = __uint_as_float(hi);
            }
    }
    __syncthreads();
#pragma unroll
    for (int g = 1; g < 4; g++) {
        if (grp == g) {
#pragma unroll
            for (int i = 0; i < 8; i++)
#pragma unroll
                for (int jp = 0; jp < 4; jp++) {
                    unsigned int lo, hi;
                    asm("mov.b64 {%0,%1}, %2;" : "=r"(lo), "=r"(hi) : "l"(acc[i][jp]));
                    Ms[(ty * 8 + i) * 64 + tx * 8 + jp * 2]     += __uint_as_float(lo);
                    Ms[(ty * 8 + i) * 64 + tx * 8 + jp * 2 + 1] += __uint_as_float(hi);
                }
        }
        __syncthreads();
    }

    // ---------- Store transposed slab: part[blk][j*60+v] = Ms[v][j] ----------
    float* dst = g_part + (size_t)blockIdx.x * 3600;
    for (int e = tid; e < 3600; e += 256) {
        const int j = e / 60;
        const int v = e - j * 60;
        dst[e] = Ms[v * 64 + j];
    }
}

// ============================================================================
// Kernel 2 (fused): one CTA per output column j, 512 threads.
//   Stage 1: 8 c-lanes x 64 v-threads reduce 296 slabs (coalesced 240B rows).
//   Stage 2: Mcol -> W2^T dot -> sigmoid -> V_s dot -> column softmax.
// ============================================================================
__global__ __launch_bounds__(512)
void k2_fused(const float* __restrict__ W2,
              const float* __restrict__ b_s,
              const float* __restrict__ V_s,
              float* __restrict__ out) {
    const int j   = blockIdx.x;
    const int tid = threadIdx.x;
    const int cl  = tid >> 6;    // 0..7
    const int v   = tid & 63;    // 0..63

    __shared__ float red[64 * 8];
    __shared__ float Mcol[64];
    __shared__ float sig[64];
    __shared__ float sS[64];

    // Stage 1: c = cl + 8*i, i = 0..36  (8*37 = 296)
    float s = 0.f;
    if (v < 60) {
        const float* p = g_part + (size_t)cl * 3600 + j * 60 + v;
        float s0 = 0.f, s1 = 0.f, s2 = 0.f, s3 = 0.f;
        int i = 0;
#pragma unroll
        for (; i + 4 <= 36; i += 4) {
            s0 += p[(size_t)(i + 0) * 8 * 3600];
            s1 += p[(size_t)(i + 1) * 8 * 3600];
            s2 += p[(size_t)(i + 2) * 8 * 3600];
            s3 += p[(size_t)(i + 3) * 8 * 3600];
        }
        s0 += p[(size_t)36 * 8 * 3600];
        s = (s0 + s1) + (s2 + s3);
    }
    red[v * 8 + cl] = s;
    __syncthreads();

    if (tid < 64) {
        float m = 0.f;
#pragma unroll
        for (int c2 = 0; c2 < 8; c2++) m += red[tid * 8 + c2];
        Mcol[tid] = m;
    }
    __syncthreads();

    // Stage 2: epilogue on 60 threads
    float sg = 0.f;
    if (tid < 60) {
        const int k = tid;
        float pr = 0.f;
#pragma unroll 4
        for (int vv = 0; vv < 60; vv++) pr = fmaf(W2[vv * 60 + k], Mcol[vv], pr);
        pr += b_s[k * 60 + j];
        sg = 1.f / (1.f + expf(-pr));
    }
    if (tid < 64) sig[tid] = sg;
    __syncthreads();

    float Si = 0.f;
    if (tid < 60) {
        const float4* vr = (const float4*)(V_s + tid * 60);  // 240B rows, 16B aligned
#pragma unroll
        for (int q = 0; q < 15; q++) {
            float4 vx = vr[q];
            Si = fmaf(vx.x, sig[q * 4 + 0], Si);
            Si = fmaf(vx.y, sig[q * 4 + 1], Si);
            Si = fmaf(vx.z, sig[q * 4 + 2], Si);
            Si = fmaf(vx.w, sig[q * 4 + 3], Si);
        }
    }
    if (tid < 64) sS[tid] = (tid < 60) ? Si : -1e30f;
    __syncthreads();

    if (tid < 60) {
        float m = -1e30f;
#pragma unroll 4
        for (int i2 = 0; i2 < 60; i2++) m = fmaxf(m, sS[i2]);
        float sum = 0.f;
#pragma unroll 4
        for (int i2 = 0; i2 < 60; i2++) sum += expf(sS[i2] - m);
        out[tid * 60 + j] = expf(Si - m) / sum;
    }
}

// ============================================================================
extern "C" void kernel_launch(void* const* d_in, const int* in_sizes, int n_in,
                              void* d_out, int out_size) {
    const float* x   = (const float*)d_in[0];
    const float* W1  = (const float*)d_in[1];
    const float* W2  = (const float*)d_in[2];
    const float* W3  = (const float*)d_in[3];
    const float* b_s = (const float*)d_in[4];
    const float* V_s = (const float*)d_in[5];
    float* out = (float*)d_out;

    k1_gram<<<NC, 256>>>(x, W1, W3);
    k2_fused<<<V_DIM, 512>>>(W2, b_s, V_s, out);
}